// round 6
// baseline (speedup 1.0000x reference)
#include <cuda_runtime.h>
#include <cuda_fp16.h>
#include <cstdint>

// ============================================================================
// CIN fused kernel, GB300 sm_103 (mma.sync + ldmatrix path).
// CTA = 512 threads split into 2 INDEPENDENT 256-thread halves (2 batches
// each) with private W double-buffers and named barriers -> halves drift and
// hide each other's barrier/skew stalls.
//   A = Zt in REGISTERS: half2 x0 (resident) * h broadcast via HMUL2
//   B = W chunk (fp16 scratch) via cp.async + ldmatrix
// K-chunk = 64. Warp tile: 32 n x 64 o. Grid 128 x 512.
// ============================================================================

#define DEVINL __device__ __forceinline__

constexpr int THREADS = 512;
constexpr int NCTA    = 128;
constexpr int NCH64   = 16 + 64 + 64;     // 144 k-chunks of 64

// smem layout (bytes)
constexpr int SM_SCORE = 0;                    // 4 floats
constexpr int SM_BIAS  = 64;                   // 384 floats
constexpr int SM_LW    = 1600;                 // 384 floats
constexpr int SM_W     = 3200;                 // 4 buffers (2 halves x 2 stages)
constexpr int W_STAGE  = 20480;                // 2 sub-chunks x (128 rows x 80B)
constexpr int SM_H     = SM_W + 4 * W_STAGE;   // 85120
constexpr int H_ROWF   = 132;                  // floats per h row (pad)
constexpr int SMEM_BYTES = SM_H + 256 * H_ROWF * 4;   // 220288

// device scratch: fp16 weights
__device__ __align__(16) __half g_W0h[128 * 1024];
__device__ __align__(16) __half g_W1h[128 * 4096];
__device__ __align__(16) __half g_W2h[128 * 4096];

// ---------------- helpers ----------------
DEVINL uint32_t smem_u32(const void* p) {
    uint32_t a;
    asm("{ .reg .u64 t; cvta.to.shared.u64 t, %1; cvt.u32.u64 %0, t; }"
        : "=r"(a) : "l"(p));
    return a;
}

DEVINL void cp_async16(uint32_t dst, const void* src) {
    asm volatile("cp.async.cg.shared.global [%0], [%1], 16;"
                 :: "r"(dst), "l"(src) : "memory");
}
DEVINL void cp_commit() { asm volatile("cp.async.commit_group;" ::: "memory"); }
DEVINL void cp_wait0()  { asm volatile("cp.async.wait_group 0;" ::: "memory"); }

#define BARH(id) asm volatile("bar.sync %0, 256;" :: "r"(id) : "memory")

DEVINL uint32_t h2u(__half2 v) { return *reinterpret_cast<uint32_t*>(&v); }

DEVINL void ldsm_x4(uint32_t& b0, uint32_t& b1, uint32_t& b2, uint32_t& b3,
                    uint32_t addr) {
    asm volatile("ldmatrix.sync.aligned.m8n8.x4.shared.b16 {%0,%1,%2,%3}, [%4];"
                 : "=r"(b0), "=r"(b1), "=r"(b2), "=r"(b3) : "r"(addr));
}

DEVINL void mma16816(float* c, uint32_t a0, uint32_t a1, uint32_t a2, uint32_t a3,
                     uint32_t b0, uint32_t b1) {
    asm volatile(
        "mma.sync.aligned.m16n8k16.row.col.f32.f16.f16.f32 "
        "{%0,%1,%2,%3}, {%4,%5,%6,%7}, {%8,%9}, {%0,%1,%2,%3};"
        : "+f"(c[0]), "+f"(c[1]), "+f"(c[2]), "+f"(c[3])
        : "r"(a0), "r"(a1), "r"(a2), "r"(a3), "r"(b0), "r"(b1));
}

// ============================================================================
// prep: fp32 W -> fp16 scratch
// ============================================================================
__global__ void cin_w2h(const float* __restrict__ W0,
                        const float* __restrict__ W1,
                        const float* __restrict__ W2) {
    int i = blockIdx.x * blockDim.x + threadIdx.x;
    constexpr int S0 = 128 * 1024;
    constexpr int S1 = 128 * 4096;
    if (i < S0)               g_W0h[i] = __float2half_rn(W0[i]);
    else if (i < S0 + S1)     g_W1h[i - S0] = __float2half_rn(W1[i - S0]);
    else if (i < S0 + 2 * S1) g_W2h[i - S0 - S1] = __float2half_rn(W2[i - S0 - S1]);
}

// W chunk-64 fetch by one half's 256 threads: row = t>>1, two 16B segs each,
// for both 32-col sub-chunks.
DEVINL void issue_w64(int gc, uint32_t wdst, int t256) {
    const __half* src; int kw;
    if (gc < 16)      { src = g_W0h + gc * 64;         kw = 1024; }
    else if (gc < 80) { src = g_W1h + (gc - 16) * 64;  kw = 4096; }
    else              { src = g_W2h + (gc - 80) * 64;  kw = 4096; }
    int r = t256 >> 1, j = (t256 & 1) * 2;
    const __half* s0 = src + (size_t)r * kw + j * 8;
    uint32_t d0 = wdst + (uint32_t)r * 80 + (uint32_t)j * 16;
    cp_async16(d0,           s0);
    cp_async16(d0 + 16u,     s0 + 8);
    cp_async16(d0 + 10240u,       s0 + 32);
    cp_async16(d0 + 10240u + 16u, s0 + 40);
    cp_commit();
}

// ============================================================================
// main fused kernel: 1 CTA = 4 batches = 2 halves x 2 batches
// ============================================================================
__global__ __launch_bounds__(THREADS, 1)
void cin_main(const float* __restrict__ x0g,
              const float* __restrict__ bias0,
              const float* __restrict__ bias1,
              const float* __restrict__ bias2,
              const float* __restrict__ lwp,
              const float* __restrict__ lbp,
              float* __restrict__ outp) {
    extern __shared__ char smemc[];
    const uint32_t sb = smem_u32(smemc);
    const int tid  = threadIdx.x;
    const int lane = tid & 31;
    const int half = tid >> 8;          // 0 or 1
    const int t256 = tid & 255;
    const int w8   = t256 >> 5;         // warp within half: 0..7
    const int b_base = blockIdx.x * 4;
    const int barid  = half + 1;

    const uint32_t wbase = sb + SM_W + (uint32_t)half * (2 * W_STAGE);

    // prefetch first W chunk (each half its own copy)
    issue_w64(0, wbase, t256);

    // bias / lw to smem
    {
        const float* bptrs[3] = { bias0, bias1, bias2 };
        float* biasS = (float*)(smemc + SM_BIAS);
        float* lwS   = (float*)(smemc + SM_LW);
        for (int i = tid; i < 384; i += THREADS) {
            biasS[i] = bptrs[i >> 7][i & 127];
            lwS[i]   = lwp[i];
        }
    }
    if (tid < 4) ((float*)(smemc + SM_SCORE))[tid] = 0.0f;

    float* hS = (float*)(smemc + SM_H);
    // layer-0 h: row R = 64*lb + d (lb = local batch 0..3), h[R][m] = x0[...]
    for (int i = tid; i < 256 * 32; i += THREADS) {
        int m = i >> 8, R = i & 255;
        hS[(size_t)R * H_ROWF + m] =
            x0g[(((size_t)(b_base + (R >> 6))) * 32 + m) * 64 + (R & 63)];
    }

    // ---- per-thread geometry (within half) ----
    const int wn = w8 & 3;          // n block (32 of this half's 128 rows)
    const int wo = w8 >> 2;         // o half (64 outputs)
    const int r  = lane >> 2;
    const int q  = lane & 3;
    const int lb = 2 * half + (wn >> 1);        // local batch 0..3
    const int dbase = ((wn & 1) << 5) + r;

    // x0 as half2 registers: x0h[j][i] = {x0[2q+8i], x0[2q+8i+1]} at d_j
    __half2 x0h[4][4];
    {
        const float* xb = x0g + ((size_t)(b_base + lb) * 32) * 64;
#pragma unroll
        for (int j = 0; j < 4; j++) {
            int dj = dbase + 8 * j;
#pragma unroll
            for (int i = 0; i < 4; i++) {
                int m = 2 * q + 8 * i;
                x0h[j][i] = __floats2half2_rn(xb[(size_t)m * 64 + dj],
                                              xb[(size_t)(m + 1) * 64 + dj]);
            }
        }
    }

    // h row pointers: global row R = 128*half + 32*wn + r + 8j
    float* hrow0 = hS + (size_t)(128 * half + 32 * wn + r) * H_ROWF;
    float* hrow1 = hrow0 + 8 * H_ROWF;
    float* hrow2 = hrow0 + 16 * H_ROWF;
    float* hrow3 = hrow0 + 24 * H_ROWF;

    // ldmatrix fragment base (within this warp's 64-o half of its W buffer)
    const int mi = lane >> 3;
    const uint32_t lm_base = (uint32_t)(wo * 5120 +
                             ((mi >> 1) * 8 + (lane & 7)) * 80 + (mi & 1) * 16);

    float acc[16][4];
#pragma unroll
    for (int t = 0; t < 16; t++)
#pragma unroll
        for (int c = 0; c < 4; c++) acc[t][c] = 0.0f;

    float score = 0.0f;
    int gc = 0;
    __syncthreads();   // h init + score init visible (only global sync)

    for (int lay = 0; lay < 3; lay++) {
        const int nch = (lay == 0) ? 16 : 64;
        for (int ch = 0; ch < nch; ch++, gc++) {
            const int buf = gc & 1;
            cp_wait0();
            BARH(barid);                     // W[buf] visible within half
            if (gc + 1 < NCH64)
                issue_w64(gc + 1, wbase + (uint32_t)(buf ^ 1) * W_STAGE, t256);

            const uint32_t wbu = wbase + (uint32_t)buf * W_STAGE + lm_base;

            // h values for this chunk's two k-rows, 4 n-rows
            float2 hf0 = *(const float2*)(hrow0 + 2 * ch);
            float2 hf1 = *(const float2*)(hrow1 + 2 * ch);
            float2 hf2 = *(const float2*)(hrow2 + 2 * ch);
            float2 hf3 = *(const float2*)(hrow3 + 2 * ch);
            __half2 hb[4][2];
            hb[0][0] = __half2half2(__float2half_rn(hf0.x));
            hb[0][1] = __half2half2(__float2half_rn(hf0.y));
            hb[1][0] = __half2half2(__float2half_rn(hf1.x));
            hb[1][1] = __half2half2(__float2half_rn(hf1.y));
            hb[2][0] = __half2half2(__float2half_rn(hf2.x));
            hb[2][1] = __half2half2(__float2half_rn(hf2.y));
            hb[3][0] = __half2half2(__float2half_rn(hf3.x));
            hb[3][1] = __half2half2(__float2half_rn(hf3.y));

#pragma unroll
            for (int s = 0; s < 4; s++) {
                const int sub = s >> 1;      // which k-row of the pair
                const int sh  = s & 1;       // m half: [0,16) or [16,32)
                uint32_t a00 = h2u(__hmul2(hb[0][sub], x0h[0][2 * sh]));
                uint32_t a01 = h2u(__hmul2(hb[1][sub], x0h[1][2 * sh]));
                uint32_t a02 = h2u(__hmul2(hb[0][sub], x0h[0][2 * sh + 1]));
                uint32_t a03 = h2u(__hmul2(hb[1][sub], x0h[1][2 * sh + 1]));
                uint32_t a10 = h2u(__hmul2(hb[2][sub], x0h[2][2 * sh]));
                uint32_t a11 = h2u(__hmul2(hb[3][sub], x0h[3][2 * sh]));
                uint32_t a12 = h2u(__hmul2(hb[2][sub], x0h[2][2 * sh + 1]));
                uint32_t a13 = h2u(__hmul2(hb[3][sub], x0h[3][2 * sh + 1]));
                const uint32_t lma = wbu + (uint32_t)sub * 10240u +
                                     (uint32_t)sh * 32u;
#pragma unroll
                for (int g = 0; g < 4; g++) {
                    uint32_t b0, b1, b2, b3;
                    ldsm_x4(b0, b1, b2, b3, lma + (uint32_t)g * 1280);
                    mma16816(acc[2 * g],         a00, a01, a02, a03, b0, b1);
                    mma16816(acc[2 * g + 1],     a00, a01, a02, a03, b2, b3);
                    mma16816(acc[8 + 2 * g],     a10, a11, a12, a13, b0, b1);
                    mma16816(acc[8 + 2 * g + 1], a10, a11, a12, a13, b2, b3);
                }
            }
        }

        // -------- epilogue (per half) --------
        BARH(barid);   // half's warps done reading h for this layer
        {
            const float* biasS = (const float*)(smemc + SM_BIAS) + lay * 128;
            const float* lwS   = (const float*)(smemc + SM_LW) + lay * 128;
            float sc = 0.0f;
#pragma unroll
            for (int T = 0; T < 2; T++) {
                float* ha  = T ? hrow2 : hrow0;
                float* hb2 = T ? hrow3 : hrow1;
#pragma unroll
                for (int go = 0; go < 8; go++) {
                    const int t = 8 * T + go;
                    const int o = 64 * wo + 8 * go + 2 * q;
                    const float bv0 = biasS[o], bv1 = biasS[o + 1];
                    float v00 = fmaxf(acc[t][0] + bv0, 0.0f);
                    float v01 = fmaxf(acc[t][1] + bv1, 0.0f);
                    float v10 = fmaxf(acc[t][2] + bv0, 0.0f);
                    float v11 = fmaxf(acc[t][3] + bv1, 0.0f);
                    sc += (v00 + v10) * lwS[o] + (v01 + v11) * lwS[o + 1];
                    if (lay < 2) {
                        *(float2*)(ha + o)  = make_float2(v00, v01);
                        *(float2*)(hb2 + o) = make_float2(v10, v11);
                    }
                    acc[t][0] = acc[t][1] = acc[t][2] = acc[t][3] = 0.0f;
                }
            }
            score += sc;
        }
        // h writes -> next layer's reads ordered by the BARH at next chunk
    }

    // warp-reduce score, accumulate per-batch
#pragma unroll
    for (int off = 16; off; off >>= 1)
        score += __shfl_xor_sync(0xFFFFFFFFu, score, off);
    if (lane == 0) atomicAdd((float*)(smemc + SM_SCORE) + lb, score);
    __syncthreads();

    if (tid < 4) outp[b_base + tid] = ((float*)(smemc + SM_SCORE))[tid] + lbp[0];
}

extern "C" void kernel_launch(void* const* d_in, const int* in_sizes, int n_in,
                              void* d_out, int out_size) {
    const float* x0 = (const float*)d_in[0];
    const float* W0 = (const float*)d_in[1];
    const float* b0 = (const float*)d_in[2];
    const float* W1 = (const float*)d_in[3];
    const float* b1 = (const float*)d_in[4];
    const float* W2 = (const float*)d_in[5];
    const float* b2 = (const float*)d_in[6];
    const float* lw = (const float*)d_in[7];
    const float* lb = (const float*)d_in[8];
    float* outp = (float*)d_out;

    constexpr int TOTW = 128 * (1024 + 4096 + 4096);
    cin_w2h<<<(TOTW + 1023) / 1024, 1024>>>(W0, W1, W2);

    static_assert(SMEM_BYTES <= 227 * 1024, "smem");
    cudaFuncSetAttribute(cin_main, cudaFuncAttributeMaxDynamicSharedMemorySize,
                         SMEM_BYTES);
    cin_main<<<NCTA, THREADS, SMEM_BYTES>>>(x0, b0, b1, b2, lw, lb, outp);
}